// round 4
// baseline (speedup 1.0000x reference)
#include <cuda_runtime.h>
#include <cstdint>

// Problem constants
#define BATCH   8
#define CIN     32
#define COUT    64
#define HW      (512 * 512)          // 262144, divisible by TILE
#define NPIX    (BATCH * HW)         // 2,097,152 pixels
#define TILE    256                  // pixels per block
#define NTHREADS 256

// Shared: wn [CIN][COUT] natural (8 KB) + bs [COUT]
#define SMEM_FLOATS (CIN * COUT + COUT)

__device__ __forceinline__ void fma2(unsigned long long& d,
                                     unsigned long long a,
                                     unsigned long long b) {
    asm("fma.rn.f32x2 %0, %1, %2, %0;" : "+l"(d) : "l"(a), "l"(b));
}

__device__ __forceinline__ unsigned long long dup2(float v) {
    unsigned long long r;
    asm("mov.b64 %0, {%1, %1};" : "=l"(r) : "f"(v));
    return r;
}

__device__ __forceinline__ unsigned long long add2(unsigned long long a,
                                                   unsigned long long b) {
    unsigned long long r;
    asm("add.rn.f32x2 %0, %1, %2;" : "=l"(r) : "l"(a), "l"(b));
    return r;
}

__global__ void __launch_bounds__(NTHREADS, 2)
spconv_pw_kernel(const float* __restrict__ x,
                 const float* __restrict__ Wg,
                 const float* __restrict__ bias,
                 float* __restrict__ out) {
    extern __shared__ float sm[];
    float* wn = sm;                 // [CIN][COUT] natural
    float* bs = wn + CIN * COUT;    // [COUT]

    const int tid = threadIdx.x;

    const long long p0  = (long long)blockIdx.x * TILE;
    const int       b   = (int)(p0 / HW);
    const int       hw0 = (int)(p0 % HW);

    // ---- stage weights + bias (only smem use) ----
    #pragma unroll
    for (int i = tid; i < CIN * COUT / 4; i += NTHREADS) {
        ((float4*)wn)[i] = ((const float4*)Wg)[i];
    }
    if (tid < COUT) bs[tid] = bias[tid];
    __syncthreads();

    // mapping: og = output group of 16 (uniform per warp), pg = pixel group of 4
    const int og = tid >> 6;   // 0..3
    const int pg = tid & 63;   // 0..63

    // acc[j][p]: output pair j (outputs og*16+2j, +2j+1), pixel p
    unsigned long long acc[8][4];
    #pragma unroll
    for (int j = 0; j < 8; ++j)
        #pragma unroll
        for (int p = 0; p < 4; ++p) acc[j][p] = 0ULL;

    unsigned m0 = 0u, m1 = 0u, m2 = 0u, m3 = 0u;
    const unsigned ABSM = 0x7FFFFFFFu;

    // x read directly from global: per-thread 4 consecutive pixels, per-warp 512B
    const float* xp = x + (long long)b * CIN * HW + hw0 + pg * 4;
    const float* wsp = wn + og * 16;

    #pragma unroll 4
    for (int c = 0; c < CIN; ++c) {
        float4 xv = *(const float4*)xp;
        xp += HW;

        m0 |= __float_as_uint(xv.x) & ABSM;
        m1 |= __float_as_uint(xv.y) & ABSM;
        m2 |= __float_as_uint(xv.z) & ABSM;
        m3 |= __float_as_uint(xv.w) & ABSM;

        unsigned long long xx0 = dup2(xv.x);
        unsigned long long xx1 = dup2(xv.y);
        unsigned long long xx2 = dup2(xv.z);
        unsigned long long xx3 = dup2(xv.w);

        // 16 natural weights for this channel: 4 broadcast LDS.128
        const ulonglong2* wrow = (const ulonglong2*)(wsp + c * COUT);
        ulonglong2 wA = wrow[0];   // (w0,w1),(w2,w3)
        ulonglong2 wB = wrow[1];   // (w4,w5),(w6,w7)
        ulonglong2 wC = wrow[2];   // (w8,w9),(w10,w11)
        ulonglong2 wD = wrow[3];   // (w12,w13),(w14,w15)
        unsigned long long wv[8] = { wA.x, wA.y, wB.x, wB.y, wC.x, wC.y, wD.x, wD.y };

        #pragma unroll
        for (int j = 0; j < 8; ++j) {
            fma2(acc[j][0], xx0, wv[j]);
            fma2(acc[j][1], xx1, wv[j]);
            fma2(acc[j][2], xx2, wv[j]);
            fma2(acc[j][3], xx3, wv[j]);
        }
    }

    const bool a0 = (m0 != 0u);
    const bool a1 = (m1 != 0u);
    const bool a2 = (m2 != 0u);
    const bool a3 = (m3 != 0u);

    // ---- epilogue ----
    float* ob = out + (long long)b * COUT * HW + hw0 + pg * 4;
    const unsigned long long* bp = (const unsigned long long*)(bs + og * 16);

    #pragma unroll
    for (int j = 0; j < 8; ++j) {
        unsigned long long bj = bp[j];
        unsigned long long s0 = a0 ? add2(acc[j][0], bj) : 0ULL;
        unsigned long long s1 = a1 ? add2(acc[j][1], bj) : 0ULL;
        unsigned long long s2 = a2 ? add2(acc[j][2], bj) : 0ULL;
        unsigned long long s3 = a3 ? add2(acc[j][3], bj) : 0ULL;

        float2 f0 = *(float2*)&s0;
        float2 f1 = *(float2*)&s1;
        float2 f2 = *(float2*)&s2;
        float2 f3 = *(float2*)&s3;

        int o0 = og * 16 + 2 * j;
        *(float4*)(ob + (long long)o0 * HW)       = make_float4(f0.x, f1.x, f2.x, f3.x);
        *(float4*)(ob + (long long)(o0 + 1) * HW) = make_float4(f0.y, f1.y, f2.y, f3.y);
    }
}

extern "C" void kernel_launch(void* const* d_in, const int* in_sizes, int n_in,
                              void* d_out, int out_size) {
    const float* x  = (const float*)d_in[0];
    const float* Wg = (const float*)d_in[1];
    const float* bi = (const float*)d_in[2];
    float* out = (float*)d_out;

    const int smem_bytes = SMEM_FLOATS * (int)sizeof(float);  // ~8.5 KB
    cudaFuncSetAttribute(spconv_pw_kernel,
                         cudaFuncAttributeMaxDynamicSharedMemorySize, smem_bytes);

    const int grid = NPIX / TILE;   // 8192
    spconv_pw_kernel<<<grid, NTHREADS, smem_bytes>>>(x, Wg, bi, out);
}

// round 5
// speedup vs baseline: 1.5306x; 1.5306x over previous
#include <cuda_runtime.h>
#include <cstdint>

// Problem constants
#define BATCH   8
#define CIN     32
#define COUT    64
#define HW      (512 * 512)          // 262144, divisible by TILE
#define NPIX    (BATCH * HW)         // 2,097,152 pixels
#define TILE    256                  // pixels per block
#define NTHREADS 256

// Shared layout:
//   xs : float [CIN][TILE] = 8192 floats (32 KB)
//   wn : float [CIN][COUT] = 2048 floats (8 KB), natural order
//   bs : float [COUT]
#define SMEM_FLOATS (CIN * TILE + CIN * COUT + COUT)

__device__ __forceinline__ void fma2(unsigned long long& d,
                                     unsigned long long a,
                                     unsigned long long b) {
    asm("fma.rn.f32x2 %0, %1, %2, %0;" : "+l"(d) : "l"(a), "l"(b));
}

__device__ __forceinline__ unsigned long long dup2(float v) {
    unsigned long long r;
    asm("mov.b64 %0, {%1, %1};" : "=l"(r) : "f"(v));
    return r;
}

__device__ __forceinline__ unsigned long long add2(unsigned long long a,
                                                   unsigned long long b) {
    unsigned long long r;
    asm("add.rn.f32x2 %0, %1, %2;" : "=l"(r) : "l"(a), "l"(b));
    return r;
}

__global__ void __launch_bounds__(NTHREADS, 2)
spconv_pw_kernel(const float* __restrict__ x,
                 const float* __restrict__ Wg,
                 const float* __restrict__ bias,
                 float* __restrict__ out) {
    extern __shared__ float sm[];
    float* xs = sm;                          // [CIN][TILE]
    float* wn = sm + CIN * TILE;             // [CIN][COUT] natural
    float* bs = wn + CIN * COUT;             // [COUT]

    const int tid = threadIdx.x;

    const long long p0  = (long long)blockIdx.x * TILE;
    const int       b   = (int)(p0 / HW);
    const int       hw0 = (int)(p0 % HW);

    // ---- stage weights (natural) + bias ----
    #pragma unroll
    for (int i = tid; i < CIN * COUT / 4; i += NTHREADS) {
        ((float4*)wn)[i] = ((const float4*)Wg)[i];
    }
    if (tid < COUT) bs[tid] = bias[tid];

    // ---- stage x tile: 32 channels x 256 pixels, batched float4 LDGs ----
    const float* xb = x + (long long)b * CIN * HW + hw0;
    #pragma unroll
    for (int i = tid; i < CIN * (TILE / 4); i += NTHREADS) {
        int c = i >> 6;      // i / (TILE/4)
        int q = i & 63;      // i % (TILE/4)
        float4 v = *(const float4*)(xb + (long long)c * HW + q * 4);
        *(float4*)(&xs[c * TILE + q * 4]) = v;
    }
    __syncthreads();

    // mapping: og = output group of 16 (uniform per warp -> broadcast w loads),
    //          pg = pixel group of 4
    const int og = tid >> 6;   // 0..3
    const int pg = tid & 63;   // 0..63

    // acc[j][p]: output pair j (outputs og*16+2j, +2j+1), pixel p
    unsigned long long acc[8][4];
    #pragma unroll
    for (int j = 0; j < 8; ++j)
        #pragma unroll
        for (int p = 0; p < 4; ++p) acc[j][p] = 0ULL;

    unsigned m0 = 0u, m1 = 0u, m2 = 0u, m3 = 0u;
    const unsigned ABSM = 0x7FFFFFFFu;

    const float* xsp = xs + pg * 4;
    const float* wsp = wn + og * 16;

    #pragma unroll 8
    for (int c = 0; c < CIN; ++c) {
        // 4 pixels of x: one LDS.128 (distinct 16B per lane)
        float4 xv = *(const float4*)(xsp + c * TILE);

        m0 |= __float_as_uint(xv.x) & ABSM;
        m1 |= __float_as_uint(xv.y) & ABSM;
        m2 |= __float_as_uint(xv.z) & ABSM;
        m3 |= __float_as_uint(xv.w) & ABSM;

        unsigned long long xx0 = dup2(xv.x);
        unsigned long long xx1 = dup2(xv.y);
        unsigned long long xx2 = dup2(xv.z);
        unsigned long long xx3 = dup2(xv.w);

        // 16 natural weights for this channel: 4 broadcast LDS.128
        const ulonglong2* wrow = (const ulonglong2*)(wsp + c * COUT);
        ulonglong2 wA = wrow[0];
        ulonglong2 wB = wrow[1];
        ulonglong2 wC = wrow[2];
        ulonglong2 wD = wrow[3];
        unsigned long long wv[8] = { wA.x, wA.y, wB.x, wB.y, wC.x, wC.y, wD.x, wD.y };

        #pragma unroll
        for (int j = 0; j < 8; ++j) {
            fma2(acc[j][0], xx0, wv[j]);
            fma2(acc[j][1], xx1, wv[j]);
            fma2(acc[j][2], xx2, wv[j]);
            fma2(acc[j][3], xx3, wv[j]);
        }
    }

    const bool a0 = (m0 != 0u);
    const bool a1 = (m1 != 0u);
    const bool a2 = (m2 != 0u);
    const bool a3 = (m3 != 0u);

    // ---- epilogue: bias where active, zero elsewhere; STG.128 per output row ----
    float* ob = out + (long long)b * COUT * HW + hw0 + pg * 4;
    const unsigned long long* bp = (const unsigned long long*)(bs + og * 16);

    #pragma unroll
    for (int j = 0; j < 8; ++j) {
        unsigned long long bj = bp[j];
        unsigned long long s0 = a0 ? add2(acc[j][0], bj) : 0ULL;
        unsigned long long s1 = a1 ? add2(acc[j][1], bj) : 0ULL;
        unsigned long long s2 = a2 ? add2(acc[j][2], bj) : 0ULL;
        unsigned long long s3 = a3 ? add2(acc[j][3], bj) : 0ULL;

        float2 f0 = *(float2*)&s0;
        float2 f1 = *(float2*)&s1;
        float2 f2 = *(float2*)&s2;
        float2 f3 = *(float2*)&s3;

        int o0 = og * 16 + 2 * j;
        *(float4*)(ob + (long long)o0 * HW)       = make_float4(f0.x, f1.x, f2.x, f3.x);
        *(float4*)(ob + (long long)(o0 + 1) * HW) = make_float4(f0.y, f1.y, f2.y, f3.y);
    }
}

extern "C" void kernel_launch(void* const* d_in, const int* in_sizes, int n_in,
                              void* d_out, int out_size) {
    const float* x  = (const float*)d_in[0];
    const float* Wg = (const float*)d_in[1];
    const float* bi = (const float*)d_in[2];
    float* out = (float*)d_out;

    const int smem_bytes = SMEM_FLOATS * (int)sizeof(float);  // ~40.5 KB
    cudaFuncSetAttribute(spconv_pw_kernel,
                         cudaFuncAttributeMaxDynamicSharedMemorySize, smem_bytes);

    const int grid = NPIX / TILE;   // 8192
    spconv_pw_kernel<<<grid, NTHREADS, smem_bytes>>>(x, Wg, bi, out);
}

// round 7
// speedup vs baseline: 1.6664x; 1.0887x over previous
#include <cuda_runtime.h>
#include <cuda_bf16.h>
#include <cstdint>

#define BATCH 8
#define CIN   32
#define COUT  64
#define HW    (512 * 512)
#define NPIX  (BATCH * HW)
#define TILE  128
#define NT    128

// xs/wt row pitch: 40 bf16 = 80 bytes (frag LDS bank-perfect: 20g+t distinct mod 32)
#define XPITCH 80

// smem byte offsets (all 16B aligned)
#define RAW_OFF 0                       // raw x  [32][128] f32 = 16384
#define XHI_OFF 16384                   // 128 * 80 = 10240
#define XLO_OFF (XHI_OFF + 10240)
#define WHI_OFF (XLO_OFF + 10240)       // 64 * 80 = 5120
#define WLO_OFF (WHI_OFF + 5120)
#define BS_OFF  (WLO_OFF + 5120)        // 256
#define ACT_OFF (BS_OFF + 256)          // 128 * 4 = 512
#define SMEM_TOT (ACT_OFF + 512)        // 47872 < 48KB -> static shared OK

__device__ __forceinline__ void mma16816(float* c, const uint32_t* a, const uint32_t* b) {
    asm volatile(
        "mma.sync.aligned.m16n8k16.row.col.f32.bf16.bf16.f32 "
        "{%0,%1,%2,%3}, {%4,%5,%6,%7}, {%8,%9}, {%0,%1,%2,%3};"
        : "+f"(c[0]), "+f"(c[1]), "+f"(c[2]), "+f"(c[3])
        : "r"(a[0]), "r"(a[1]), "r"(a[2]), "r"(a[3]), "r"(b[0]), "r"(b[1]));
}

// pack two floats as bf16x2: low half = e0, high half = e1
__device__ __forceinline__ uint32_t pack_bf16(__nv_bfloat16 e0, __nv_bfloat16 e1) {
    __nv_bfloat162 v;
    v.x = e0; v.y = e1;
    return *(uint32_t*)&v;
}

__global__ void __launch_bounds__(NT)
spconv_mma_kernel(const float* __restrict__ x,
                  const float* __restrict__ Wg,
                  const float* __restrict__ bias,
                  float* __restrict__ out) {
    __shared__ __align__(16) char smc[SMEM_TOT];

    const int tid = threadIdx.x;
    const long long p0 = (long long)blockIdx.x * TILE;
    const int b   = (int)(p0 / HW);
    const int hw0 = (int)(p0 % HW);

    // ---- pass 1: coalesced x -> raw smem [ch][128px] (STS.128, conflict-free) ----
    const float* xb = x + (long long)b * CIN * HW + hw0;
    #pragma unroll
    for (int it = 0; it < 8; ++it) {
        int i = tid + it * NT;
        int c = i >> 5;      // channel
        int q = i & 31;      // pixel quad
        float4 v = *(const float4*)(xb + (long long)c * HW + 4 * q);
        *(float4*)(smc + RAW_OFF + (c * 128 + 4 * q) * 4) = v;
    }

    // ---- stage W^T hi/lo: wt[out][ch] bf16, pitch 80B ----
    {
        const int o    = tid >> 1;
        const int half = tid & 1;
        uint32_t hp[8], lp[8];
        #pragma unroll
        for (int j = 0; j < 8; ++j) {
            int ch = half * 16 + 2 * j;
            float w0 = Wg[ch * COUT + o];
            float w1 = Wg[(ch + 1) * COUT + o];
            __nv_bfloat16 h0 = __float2bfloat16(w0);
            __nv_bfloat16 h1 = __float2bfloat16(w1);
            __nv_bfloat16 l0 = __float2bfloat16(w0 - __bfloat162float(h0));
            __nv_bfloat16 l1 = __float2bfloat16(w1 - __bfloat162float(h1));
            hp[j] = pack_bf16(h0, h1);
            lp[j] = pack_bf16(l0, l1);
        }
        char* wh = smc + WHI_OFF + o * XPITCH + half * 32;
        char* wl = smc + WLO_OFF + o * XPITCH + half * 32;
        ((uint4*)wh)[0] = make_uint4(hp[0], hp[1], hp[2], hp[3]);
        ((uint4*)wh)[1] = make_uint4(hp[4], hp[5], hp[6], hp[7]);
        ((uint4*)wl)[0] = make_uint4(lp[0], lp[1], lp[2], lp[3]);
        ((uint4*)wl)[1] = make_uint4(lp[4], lp[5], lp[6], lp[7]);
    }
    if (tid < COUT) ((float*)(smc + BS_OFF))[tid] = bias[tid];

    __syncthreads();

    // ---- pass 2: thread owns pixel `tid`: mask + bf16 hi/lo rows ----
    {
        const int px = tid;
        float xv[32];
        unsigned m = 0u;
        #pragma unroll
        for (int c = 0; c < 32; ++c) {
            xv[c] = *(const float*)(smc + RAW_OFF + (c * 128 + px) * 4);
            m |= __float_as_uint(xv[c]) & 0x7FFFFFFFu;
        }
        ((uint32_t*)(smc + ACT_OFF))[px] = m;

        uint32_t hp[16], lp[16];
        #pragma unroll
        for (int j = 0; j < 16; ++j) {
            float a0 = xv[2 * j], a1 = xv[2 * j + 1];
            __nv_bfloat16 h0 = __float2bfloat16(a0);
            __nv_bfloat16 h1 = __float2bfloat16(a1);
            __nv_bfloat16 l0 = __float2bfloat16(a0 - __bfloat162float(h0));
            __nv_bfloat16 l1 = __float2bfloat16(a1 - __bfloat162float(h1));
            hp[j] = pack_bf16(h0, h1);
            lp[j] = pack_bf16(l0, l1);
        }
        char* xh = smc + XHI_OFF + px * XPITCH;
        char* xl = smc + XLO_OFF + px * XPITCH;
        #pragma unroll
        for (int j = 0; j < 4; ++j) {
            ((uint4*)xh)[j] = make_uint4(hp[4*j], hp[4*j+1], hp[4*j+2], hp[4*j+3]);
            ((uint4*)xl)[j] = make_uint4(lp[4*j], lp[4*j+1], lp[4*j+2], lp[4*j+3]);
        }
    }
    __syncthreads();

    // ---- mainloop: warp = 32px x 64out; m16n8k16, 3-term bf16 split ----
    const int w = tid >> 5;
    const int l = tid & 31;
    const int g = l >> 2;     // groupID
    const int t = l & 3;      // thread-in-group
    const int rowbase = 32 * w;

    float acc[2][8][4];
    #pragma unroll
    for (int m = 0; m < 2; ++m)
        #pragma unroll
        for (int n = 0; n < 8; ++n)
            #pragma unroll
            for (int r = 0; r < 4; ++r) acc[m][n][r] = 0.0f;

    const char* XH = smc + XHI_OFF;
    const char* XL = smc + XLO_OFF;
    const char* WH = smc + WHI_OFF;
    const char* WL = smc + WLO_OFF;

    #pragma unroll
    for (int k = 0; k < 2; ++k) {
        const int cb = 32 * k + 4 * t;   // byte offset of col 16k+2t

        uint32_t ah[2][4], al[2][4];
        #pragma unroll
        for (int m = 0; m < 2; ++m) {
            int base = (rowbase + 16 * m + g) * XPITCH + cb;
            ah[m][0] = *(const uint32_t*)(XH + base);
            ah[m][1] = *(const uint32_t*)(XH + base + 8 * XPITCH);
            ah[m][2] = *(const uint32_t*)(XH + base + 16);
            ah[m][3] = *(const uint32_t*)(XH + base + 8 * XPITCH + 16);
            al[m][0] = *(const uint32_t*)(XL + base);
            al[m][1] = *(const uint32_t*)(XL + base + 8 * XPITCH);
            al[m][2] = *(const uint32_t*)(XL + base + 16);
            al[m][3] = *(const uint32_t*)(XL + base + 8 * XPITCH + 16);
        }

        #pragma unroll
        for (int nb = 0; nb < 2; ++nb) {
            uint32_t bh[4][2], bl[4][2];
            #pragma unroll
            for (int nn = 0; nn < 4; ++nn) {
                int o = 8 * (4 * nb + nn) + g;
                int off = o * XPITCH + cb;
                bh[nn][0] = *(const uint32_t*)(WH + off);
                bh[nn][1] = *(const uint32_t*)(WH + off + 16);
                bl[nn][0] = *(const uint32_t*)(WL + off);
                bl[nn][1] = *(const uint32_t*)(WL + off + 16);
            }
            // 3 split terms; dep distance 8 on each accumulator
            #pragma unroll
            for (int nn = 0; nn < 4; ++nn)
                #pragma unroll
                for (int m = 0; m < 2; ++m)
                    mma16816(acc[m][4 * nb + nn], ah[m], bh[nn]);
            #pragma unroll
            for (int nn = 0; nn < 4; ++nn)
                #pragma unroll
                for (int m = 0; m < 2; ++m)
                    mma16816(acc[m][4 * nb + nn], ah[m], bl[nn]);
            #pragma unroll
            for (int nn = 0; nn < 4; ++nn)
                #pragma unroll
                for (int m = 0; m < 2; ++m)
                    mma16816(acc[m][4 * nb + nn], al[m], bh[nn]);
        }
    }

    // ---- epilogue: bias + per-pixel mask, scalar STG (full 32B sectors) ----
    const uint32_t* actv = (const uint32_t*)(smc + ACT_OFF);
    const float*    bs   = (const float*)(smc + BS_OFF);
    float* ob = out + (long long)b * COUT * HW + hw0;

    #pragma unroll
    for (int m = 0; m < 2; ++m) {
        int px0 = rowbase + 16 * m + g;
        int px1 = px0 + 8;
        bool A0 = actv[px0] != 0u;
        bool A1 = actv[px1] != 0u;
        #pragma unroll
        for (int n = 0; n < 8; ++n) {
            int o = 8 * n + 2 * t;
            float2 bv = *(const float2*)(bs + o);
            ob[(long long)o * HW + px0]       = A0 ? acc[m][n][0] + bv.x : 0.0f;
            ob[(long long)(o + 1) * HW + px0] = A0 ? acc[m][n][1] + bv.y : 0.0f;
            ob[(long long)o * HW + px1]       = A1 ? acc[m][n][2] + bv.x : 0.0f;
            ob[(long long)(o + 1) * HW + px1] = A1 ? acc[m][n][3] + bv.y : 0.0f;
        }
    }
}

extern "C" void kernel_launch(void* const* d_in, const int* in_sizes, int n_in,
                              void* d_out, int out_size) {
    const float* x  = (const float*)d_in[0];
    const float* Wg = (const float*)d_in[1];
    const float* bi = (const float*)d_in[2];
    float* out = (float*)d_out;

    const int grid = NPIX / TILE;   // 16384
    spconv_mma_kernel<<<grid, NT>>>(x, Wg, bi, out);
}

// round 8
// speedup vs baseline: 1.7785x; 1.0673x over previous
#include <cuda_runtime.h>
#include <cuda_bf16.h>
#include <cstdint>

#define BATCH 8
#define CIN   32
#define COUT  64
#define HW    (512 * 512)
#define NPIX  (BATCH * HW)
#define TILE  128
#define NT    128

// W rows pitch: 40 bf16 = 80 bytes (mainloop B LDS.32 bank-perfect: 20o+t distinct mod 32)
#define XPITCH 80

// smem byte offsets
#define WHI_OFF 0                     // 64 * 80 = 5120
#define WLO_OFF 5120
#define BS_OFF  10240                 // 256B
#define SMEM_TOT (BS_OFF + 256)

__device__ __forceinline__ void mma16816(float* c, const uint32_t* a, const uint32_t* b) {
    asm volatile(
        "mma.sync.aligned.m16n8k16.row.col.f32.bf16.bf16.f32 "
        "{%0,%1,%2,%3}, {%4,%5,%6,%7}, {%8,%9}, {%0,%1,%2,%3};"
        : "+f"(c[0]), "+f"(c[1]), "+f"(c[2]), "+f"(c[3])
        : "r"(a[0]), "r"(a[1]), "r"(a[2]), "r"(a[3]), "r"(b[0]), "r"(b[1]));
}

__device__ __forceinline__ uint32_t pack_bf16(__nv_bfloat16 e0, __nv_bfloat16 e1) {
    __nv_bfloat162 v;
    v.x = e0; v.y = e1;
    return *(uint32_t*)&v;
}

__device__ __forceinline__ uint32_t pack_hi(float a, float b) {
    return pack_bf16(__float2bfloat16(a), __float2bfloat16(b));
}
__device__ __forceinline__ uint32_t pack_lo(float a, float b) {
    __nv_bfloat16 ha = __float2bfloat16(a);
    __nv_bfloat16 hb = __float2bfloat16(b);
    return pack_bf16(__float2bfloat16(a - __bfloat162float(ha)),
                     __float2bfloat16(b - __bfloat162float(hb)));
}

__global__ void __launch_bounds__(NT, 4)
spconv_mma_kernel(const float* __restrict__ x,
                  const float* __restrict__ Wg,
                  const float* __restrict__ bias,
                  float* __restrict__ out) {
    __shared__ __align__(16) char smc[SMEM_TOT];

    const int tid = threadIdx.x;
    const long long p0 = (long long)blockIdx.x * TILE;
    const int b   = (int)(p0 / HW);
    const int hw0 = (int)(p0 % HW);

    // ---- stage W^T hi/lo in smem: wt[out][ch] bf16, pitch 80B ----
    {
        const int o    = tid >> 1;
        const int half = tid & 1;
        uint32_t hp[8], lp[8];
        #pragma unroll
        for (int j = 0; j < 8; ++j) {
            int ch = half * 16 + 2 * j;
            float w0 = Wg[ch * COUT + o];
            float w1 = Wg[(ch + 1) * COUT + o];
            hp[j] = pack_hi(w0, w1);
            lp[j] = pack_lo(w0, w1);
        }
        char* wh = smc + WHI_OFF + o * XPITCH + half * 32;
        char* wl = smc + WLO_OFF + o * XPITCH + half * 32;
        ((uint4*)wh)[0] = make_uint4(hp[0], hp[1], hp[2], hp[3]);
        ((uint4*)wh)[1] = make_uint4(hp[4], hp[5], hp[6], hp[7]);
        ((uint4*)wl)[0] = make_uint4(lp[0], lp[1], lp[2], lp[3]);
        ((uint4*)wl)[1] = make_uint4(lp[4], lp[5], lp[6], lp[7]);
    }
    if (tid < COUT) ((float*)(smc + BS_OFF))[tid] = bias[tid];

    // ---- x direct from gmem, fragment layout; 32 independent LDG.32 ----
    const int w = tid >> 5;
    const int l = tid & 31;
    const int g = l >> 2;     // groupID
    const int t = l & 3;      // thread-in-group
    const int rowbase = 32 * w;

    // base: pixel rowbase+g, channel 2t
    const float* xb = x + (long long)b * CIN * HW + hw0 + rowbase + g
                        + (long long)(2 * t) * HW;

    // v[r][c]: r -> pixel rowbase+g+8r ; c -> channel 2t + dd[c]
    float v[4][8];
    #pragma unroll
    for (int r = 0; r < 4; ++r) {
        #pragma unroll
        for (int c = 0; c < 8; ++c) {
            const int dd = (c & 1) + ((c >> 1) & 1) * 8 + (c >> 2) * 16;  // 0,1,8,9,16,17,24,25
            v[r][c] = __ldg(xb + (long long)dd * HW + 8 * r);
        }
    }

    // ---- per-pixel activity masks (4 rows/thread), OR across t-quad via shfl ----
    uint32_t msk[4];
    #pragma unroll
    for (int r = 0; r < 4; ++r) {
        uint32_t m = 0u;
        #pragma unroll
        for (int c = 0; c < 8; ++c) m |= __float_as_uint(v[r][c]) & 0x7FFFFFFFu;
        m |= __shfl_xor_sync(0xFFFFFFFFu, m, 1);
        m |= __shfl_xor_sync(0xFFFFFFFFu, m, 2);
        msk[r] = m;
    }

    // ---- convert to A fragments (hi/lo), v dies here ----
    // ah[m][k][0..3]: a0=(row 2m, ch 4k..), a1=(row 2m+1), a2=(row 2m, ch+8), a3=(row 2m+1, ch+8)
    uint32_t ah[2][2][4], al[2][2][4];
    #pragma unroll
    for (int m = 0; m < 2; ++m) {
        #pragma unroll
        for (int k = 0; k < 2; ++k) {
            ah[m][k][0] = pack_hi(v[2*m][4*k],     v[2*m][4*k+1]);
            ah[m][k][1] = pack_hi(v[2*m+1][4*k],   v[2*m+1][4*k+1]);
            ah[m][k][2] = pack_hi(v[2*m][4*k+2],   v[2*m][4*k+3]);
            ah[m][k][3] = pack_hi(v[2*m+1][4*k+2], v[2*m+1][4*k+3]);
            al[m][k][0] = pack_lo(v[2*m][4*k],     v[2*m][4*k+1]);
            al[m][k][1] = pack_lo(v[2*m+1][4*k],   v[2*m+1][4*k+1]);
            al[m][k][2] = pack_lo(v[2*m][4*k+2],   v[2*m][4*k+3]);
            al[m][k][3] = pack_lo(v[2*m+1][4*k+2], v[2*m+1][4*k+3]);
        }
    }

    float acc[2][8][4];
    #pragma unroll
    for (int m = 0; m < 2; ++m)
        #pragma unroll
        for (int n = 0; n < 8; ++n)
            #pragma unroll
            for (int r = 0; r < 4; ++r) acc[m][n][r] = 0.0f;

    __syncthreads();   // W smem ready

    // ---- mainloop: 3-term bf16 split over K=32 ----
    const char* WH = smc + WHI_OFF;
    const char* WL = smc + WLO_OFF;

    #pragma unroll
    for (int k = 0; k < 2; ++k) {
        const int cb = 32 * k + 4 * t;
        #pragma unroll
        for (int nb = 0; nb < 2; ++nb) {
            uint32_t bh[4][2], bl[4][2];
            #pragma unroll
            for (int nn = 0; nn < 4; ++nn) {
                int o = 8 * (4 * nb + nn) + g;
                int off = o * XPITCH + cb;
                bh[nn][0] = *(const uint32_t*)(WH + off);
                bh[nn][1] = *(const uint32_t*)(WH + off + 16);
                bl[nn][0] = *(const uint32_t*)(WL + off);
                bl[nn][1] = *(const uint32_t*)(WL + off + 16);
            }
            #pragma unroll
            for (int nn = 0; nn < 4; ++nn)
                #pragma unroll
                for (int m = 0; m < 2; ++m)
                    mma16816(acc[m][4 * nb + nn], ah[m][k], bh[nn]);
            #pragma unroll
            for (int nn = 0; nn < 4; ++nn)
                #pragma unroll
                for (int m = 0; m < 2; ++m)
                    mma16816(acc[m][4 * nb + nn], ah[m][k], bl[nn]);
            #pragma unroll
            for (int nn = 0; nn < 4; ++nn)
                #pragma unroll
                for (int m = 0; m < 2; ++m)
                    mma16816(acc[m][4 * nb + nn], al[m][k], bh[nn]);
        }
    }

    // ---- epilogue: bias + per-pixel mask (own msk regs), scalar STG ----
    const float* bs = (const float*)(smc + BS_OFF);
    float* ob = out + (long long)b * COUT * HW + hw0;

    #pragma unroll
    for (int m = 0; m < 2; ++m) {
        int px0 = rowbase + 16 * m + g;
        int px1 = px0 + 8;
        bool A0 = msk[2 * m]     != 0u;
        bool A1 = msk[2 * m + 1] != 0u;
        #pragma unroll
        for (int n = 0; n < 8; ++n) {
            int o = 8 * n + 2 * t;
            float2 bv = *(const float2*)(bs + o);
            ob[(long long)o * HW + px0]       = A0 ? acc[m][n][0] + bv.x : 0.0f;
            ob[(long long)(o + 1) * HW + px0] = A0 ? acc[m][n][1] + bv.y : 0.0f;
            ob[(long long)o * HW + px1]       = A1 ? acc[m][n][2] + bv.x : 0.0f;
            ob[(long long)(o + 1) * HW + px1] = A1 ? acc[m][n][3] + bv.y : 0.0f;
        }
    }
}

extern "C" void kernel_launch(void* const* d_in, const int* in_sizes, int n_in,
                              void* d_out, int out_size) {
    const float* x  = (const float*)d_in[0];
    const float* Wg = (const float*)d_in[1];
    const float* bi = (const float*)d_in[2];
    float* out = (float*)d_out;

    const int grid = NPIX / TILE;   // 16384
    spconv_mma_kernel<<<grid, NT>>>(x, Wg, bi, out);
}